// round 10
// baseline (speedup 1.0000x reference)
#include <cuda_runtime.h>
#include <cstdint>

#define NB 32
#define NT 8
#define NN 512
#define NF 4
#define NH 64
#define NCO 12
#define L2E 1.442695040888963f
#define C02 (0.2f * 1.442695040888963f)

// Intermediates (device globals; no allocation allowed)
__device__ __align__(16) float4 g_acc[(size_t)NB * NT * NN];   // unnormalized (alpha @ x)
__device__ __align__(16) float  g_inv[(size_t)NB * NT * NN];   // 1/softmax-sum

__device__ __forceinline__ float ex2f(float v) {
    float r; asm("ex2.approx.f32 %0, %1;" : "=f"(r) : "f"(v)); return r;
}
__device__ __forceinline__ float rcpf(float v) {
    float r; asm("rcp.approx.f32 %0, %1;" : "=f"(r) : "f"(v)); return r;
}
__device__ __forceinline__ float sigmf(float x) {           // NaN-safe at extremes
    return rcpf(1.f + ex2f(-L2E * x));
}
__device__ __forceinline__ float tanhfast(float x) {
    const float E = ex2f(fminf(2.f * L2E * x, 80.f));
    return (E - 1.f) * rcpf(E + 1.f);
}

// ---------------------------------------------------------------------------
// Kernel 1: fused GAT as (alpha @ x). One CTA per (b,t); 512 threads.
// Thread = (j-split s = tid>>7, i-quad iq = tid&127). 4x LDG.128 batched with
// marching pointer, pre-scaled exp pipeline, smem partial reduction,
// diagonal post-fixup.
// ---------------------------------------------------------------------------
__global__ void __launch_bounds__(512, 2)
gat_kernel(const float* __restrict__ x, const float* __restrict__ adj,
           const float* __restrict__ gatW, const float* __restrict__ attS,
           const float* __restrict__ attD)
{
    extern __shared__ char smraw[];
    float4* sX   = (float4*)smraw;                        // 512 * 16B
    float2* sS2  = (float2*)(smraw + 8192);               // 512 * 8B
    float*  sRed = (float*)(smraw + 8192 + 4096);         // 16
    float*  sWsd = (float*)(smraw + 8192 + 4096 + 64);    // 8
    float*  sPart= (float*)(smraw + 8192 + 4096 + 64 + 32); // 4*128*20

    const int tid = threadIdx.x;
    const int bt  = blockIdx.x;

    const float4* xg = (const float4*)(x + (size_t)bt * NN * NF);
    sX[tid] = xg[tid];
    if (tid < 8) {
        const int f = tid & 3;
        const float* wrow = gatW + f * NH;
        const float* av   = (tid < 4) ? attS : attD;
        float s = 0.f;
        for (int h = 0; h < NH; ++h) s += wrow[h] * av[h];
        sWsd[tid] = s;
    }
    __syncthreads();

    const float4 wsv = *(const float4*)(sWsd);
    const float4 wdv = *(const float4*)(sWsd + 4);

    float asrc;
    {
        const float4 xv = sX[tid];
        asrc = xv.x * wsv.x + xv.y * wsv.y + xv.z * wsv.z + xv.w * wsv.w;
        float2 ss; ss.x = asrc * L2E; ss.y = asrc * C02;
        sS2[tid] = ss;
    }
    __syncthreads();

    // block max of asrc (any valid shift works; lrelu monotone)
    float v = asrc;
    #pragma unroll
    for (int o = 16; o; o >>= 1) v = fmaxf(v, __shfl_xor_sync(0xffffffffu, v, o));
    if ((tid & 31) == 0) sRed[tid >> 5] = v;
    __syncthreads();
    float smax = sRed[0];
    #pragma unroll
    for (int w = 1; w < 16; ++w) smax = fmaxf(smax, sRed[w]);

    const int s  = tid >> 7;        // j-split 0..3
    const int iq = tid & 127;       // i-quad
    const int i0 = iq * 4;

    float c1[4], c2[4];
    #pragma unroll
    for (int ii = 0; ii < 4; ++ii) {
        const float4 xi = sX[i0 + ii];
        const float ad = xi.x * wdv.x + xi.y * wdv.y + xi.z * wdv.z + xi.w * wdv.w;
        const float aL = ad * L2E, aL2 = ad * C02;
        const float Mlog = fmaxf(aL + smax * L2E, aL2 + smax * C02);
        c1[ii] = aL - Mlog;
        c2[ii] = aL2 - Mlog;
    }

    float ssum[4] = {0.f, 0.f, 0.f, 0.f};
    float ax[4] = {0.f, 0.f, 0.f, 0.f};
    float ay[4] = {0.f, 0.f, 0.f, 0.f};
    float az[4] = {0.f, 0.f, 0.f, 0.f};
    float aw[4] = {0.f, 0.f, 0.f, 0.f};

    const int jbeg = s * 128;
    // marching float4 pointer: row stride = 128 float4s
    const float4* pr = (const float4*)(adj + (size_t)bt * NN * NN)
                       + (size_t)jbeg * 128 + iq;

    #pragma unroll 1
    for (int j = jbeg; j < jbeg + 128; j += 4) {
        const float4 A0 = __ldg(pr);
        const float4 A1 = __ldg(pr + 128);
        const float4 A2 = __ldg(pr + 256);
        const float4 A3 = __ldg(pr + 384);
        pr += 512;
        #pragma unroll
        for (int u = 0; u < 4; ++u) {
            const float4 a = (u == 0) ? A0 : (u == 1) ? A1 : (u == 2) ? A2 : A3;
            const float2 sj = sS2[j + u];
            const float4 xj = sX[j + u];
            const float am[4] = {a.x, a.y, a.z, a.w};
            #pragma unroll
            for (int ii = 0; ii < 4; ++ii) {
                const float e = fmaxf(c1[ii] + sj.x, c2[ii] + sj.y);
                float p = ex2f(e);
                p = (am[ii] != 0.f) ? p : 0.f;
                ssum[ii] += p;
                ax[ii] += p * xj.x; ay[ii] += p * xj.y;
                az[ii] += p * xj.z; aw[ii] += p * xj.w;
            }
        }
    }

    // diagonal fixup: my split contains my quad's diagonal iff (iq>>5)==s
    if ((iq >> 5) == s) {
        const float* ap = adj + (size_t)bt * NN * NN + i0;
        #pragma unroll
        for (int ii = 0; ii < 4; ++ii) {
            const int i = i0 + ii;
            const float aii = __ldg(ap + (size_t)i * NN + ii);
            if (aii == 0.f) {
                const float2 sj = sS2[i];
                const float p = ex2f(fmaxf(c1[ii] + sj.x, c2[ii] + sj.y));
                const float4 xi = sX[i];
                ssum[ii] += p;
                ax[ii] += p * xi.x; ay[ii] += p * xi.y;
                az[ii] += p * xi.z; aw[ii] += p * xi.w;
            }
        }
    }

    float* pp = sPart + (size_t)(s * 128 + iq) * 20;
    #pragma unroll
    for (int ii = 0; ii < 4; ++ii) {
        pp[ii * 5 + 0] = ax[ii]; pp[ii * 5 + 1] = ay[ii];
        pp[ii * 5 + 2] = az[ii]; pp[ii * 5 + 3] = aw[ii];
        pp[ii * 5 + 4] = ssum[ii];
    }
    __syncthreads();

    // final reduce over splits: thread tid owns target i = tid
    const int q2 = tid >> 2, i2 = tid & 3;
    float vx = 0.f, vy = 0.f, vz = 0.f, vw = 0.f, sv = 0.f;
    #pragma unroll
    for (int s2 = 0; s2 < 4; ++s2) {
        const float* p2 = sPart + (size_t)(s2 * 128 + q2) * 20 + i2 * 5;
        vx += p2[0]; vy += p2[1]; vz += p2[2]; vw += p2[3]; sv += p2[4];
    }
    const size_t o = (size_t)bt * NN + tid;
    float4 av; av.x = vx; av.y = vy; av.z = vz; av.w = vw;
    g_acc[o] = av;
    g_inv[o] = 1.f / sv;
}

// ---------------------------------------------------------------------------
// Kernel 2: FUSED GRU recurrence + Conv2d(8->12, 3x3 SAME over [N,4]) +
// Linear(4->2). Block = (b, n-group of 64), 256 threads.
// CORRECT mapping: conv input g[b, ci, n, :] = h_{t=ci} of GRU sequence
// m = b*512 + n (channel = timestep, spatial row = sequence index).
// 66 threads each run one full recurrence (rows n0-1 .. n0+64) and write
// all 8 timesteps into their tile row's 8 channel slots.
// Sequence m reads gat data at base = (b*8 + (n>>6))*512 + (n&63)*8 + t
// (raw .view faithfulness).
// ---------------------------------------------------------------------------
__global__ void __launch_bounds__(256)
gruconv_kernel(const float* __restrict__ gatW, const float* __restrict__ Wih,
               const float* __restrict__ bih, const float* __restrict__ gbias,
               const float* __restrict__ Whh, const float* __restrict__ bhh,
               const float* __restrict__ cW, const float* __restrict__ cB,
               const float* __restrict__ oW, const float* __restrict__ oB,
               float* __restrict__ out)
{
    __shared__ float4 sG[66 * 9];        // [local row][t(0..7), pad] = h_t
    __shared__ float4 sW4[288];          // [(ci*3+kh)*12 + co] = {w0,w1,w2,0}
    __shared__ float sCB[12], sOW[8], sOB[2];
    __shared__ float sC[48], sd[12], sWhh[48], sbhh[12];

    const int tid = threadIdx.x;
    const int b   = blockIdx.x >> 3;
    const int g   = blockIdx.x & 7;
    const int n0  = g * 64;

    // conv/linear weights
    for (int k = tid; k < 288; k += 256) {
        const int co = k % 12, r = k / 12, kh = r % 3, ci = r / 3;
        const float* wp = cW + (((size_t)co * NT + ci) * 3 + kh) * 3;
        float4 w; w.x = wp[0]; w.y = wp[1]; w.z = wp[2]; w.w = 0.f;
        sW4[(ci * 3 + kh) * 12 + co] = w;
    }
    if (tid < 12) sCB[tid] = cB[tid];
    if (tid < 8)  sOW[tid] = oW[tid];
    if (tid < 2)  sOB[tid] = oB[tid];
    // GRU folded weights: C = W @ Wih^T, d = Wih@bias + bih
    if (tid < 48) {
        const int f = tid / 12, k = tid % 12;
        float sacc = 0.f;
        for (int h = 0; h < NH; ++h) sacc += gatW[f * NH + h] * Wih[k * NH + h];
        sC[f * 12 + k] = sacc;
        sWhh[tid] = Whh[tid];
    }
    if (tid < 12) {
        float sacc = bih[tid];
        for (int h = 0; h < NH; ++h) sacc += Wih[tid * NH + h] * gbias[h];
        sd[tid] = sacc;
        sbhh[tid] = bhh[tid];
    }
    // zero tile (covers boundary rows n=-1 / n=512)
    for (int k = tid; k < 594; k += 256) {
        float4 z = {0.f, 0.f, 0.f, 0.f};
        sG[k] = z;
    }
    __syncthreads();

    // ---- recurrences: 66 threads, one per tile row ----
    if (tid < 66) {
        const int n = n0 - 1 + tid;          // global sequence index
        if (n >= 0 && n < NN) {
            const int base = ((b * 8 + (n >> 6)) << 9) + (n & 63) * 8;
            float4 A[8];
            #pragma unroll
            for (int t = 0; t < NT; ++t) A[t] = g_acc[base + t];
            float inv[8];
            {
                const float4 I0 = *(const float4*)(g_inv + base);
                const float4 I1 = *(const float4*)(g_inv + base + 4);
                inv[0] = I0.x; inv[1] = I0.y; inv[2] = I0.z; inv[3] = I0.w;
                inv[4] = I1.x; inv[5] = I1.y; inv[6] = I1.z; inv[7] = I1.w;
            }
            float h[4] = {0.f, 0.f, 0.f, 0.f};
            float4* row = sG + tid * 9;
            #pragma unroll
            for (int t = 0; t < NT; ++t) {
                const float4 a = A[t];
                const float iv = inv[t];
                float gx[12];
                #pragma unroll
                for (int k = 0; k < 12; ++k)
                    gx[k] = iv * (a.x * sC[k] + a.y * sC[12 + k] + a.z * sC[24 + k] + a.w * sC[36 + k]) + sd[k];
                float hn[4];
                #pragma unroll
                for (int c = 0; c < 4; ++c) {
                    float ghr = sbhh[c]     + h[0]*sWhh[c*4]     + h[1]*sWhh[c*4+1]     + h[2]*sWhh[c*4+2]     + h[3]*sWhh[c*4+3];
                    float ghz = sbhh[4 + c] + h[0]*sWhh[(4+c)*4] + h[1]*sWhh[(4+c)*4+1] + h[2]*sWhh[(4+c)*4+2] + h[3]*sWhh[(4+c)*4+3];
                    float ghn = sbhh[8 + c] + h[0]*sWhh[(8+c)*4] + h[1]*sWhh[(8+c)*4+1] + h[2]*sWhh[(8+c)*4+2] + h[3]*sWhh[(8+c)*4+3];
                    float rr = sigmf(gx[c] + ghr);
                    float zz = sigmf(gx[4 + c] + ghz);
                    float nc = tanhfast(gx[8 + c] + rr * ghn);
                    hn[c] = (1.f - zz) * nc + zz * h[c];
                }
                #pragma unroll
                for (int c = 0; c < 4; ++c) h[c] = hn[c];
                float4 hv; hv.x = h[0]; hv.y = h[1]; hv.z = h[2]; hv.w = h[3];
                row[t] = hv;                 // channel ci = t
            }
        }
    }
    __syncthreads();

    // ---- conv + linear: 256 threads = (64 n) x (4 co-splits of 3) ----
    const int nloc = tid & 63;
    const int cos  = tid >> 6;

    float y[3][4];
    #pragma unroll
    for (int cc = 0; cc < 3; ++cc) {
        const float cb = sCB[cos * 3 + cc];
        y[cc][0] = cb; y[cc][1] = cb; y[cc][2] = cb; y[cc][3] = cb;
    }

    #pragma unroll
    for (int ci = 0; ci < NT; ++ci) {
        #pragma unroll
        for (int kh = 0; kh < 3; ++kh) {
            const float4 vv = sG[(nloc + kh) * 9 + ci];
            #pragma unroll
            for (int cc = 0; cc < 3; ++cc) {
                const float4 w4 = sW4[(ci * 3 + kh) * 12 + cos * 3 + cc];
                y[cc][0] += vv.x * w4.y + vv.y * w4.z;
                y[cc][1] += vv.x * w4.x + vv.y * w4.y + vv.z * w4.z;
                y[cc][2] += vv.y * w4.x + vv.z * w4.y + vv.w * w4.z;
                y[cc][3] += vv.z * w4.x + vv.w * w4.y;
            }
        }
    }

    const int n = n0 + nloc;
    float* op = out + (((size_t)b * NCO + cos * 3) * NN + n) * 2;
    #pragma unroll
    for (int cc = 0; cc < 3; ++cc) {
        float2 o;
        o.x = sOB[0] + y[cc][0]*sOW[0] + y[cc][1]*sOW[1] + y[cc][2]*sOW[2] + y[cc][3]*sOW[3];
        o.y = sOB[1] + y[cc][0]*sOW[4] + y[cc][1]*sOW[5] + y[cc][2]*sOW[6] + y[cc][3]*sOW[7];
        *(float2*)(op + (size_t)cc * (NN * 2)) = o;
    }
}

// ---------------------------------------------------------------------------
extern "C" void kernel_launch(void* const* d_in, const int* in_sizes, int n_in,
                              void* d_out, int out_size)
{
    const float* x        = (const float*)d_in[0];
    const float* adj      = (const float*)d_in[1];
    const float* gat_W    = (const float*)d_in[2];
    const float* att_src  = (const float*)d_in[3];
    const float* att_dst  = (const float*)d_in[4];
    const float* gat_bias = (const float*)d_in[5];
    const float* gru_Wih  = (const float*)d_in[6];
    const float* gru_Whh  = (const float*)d_in[7];
    const float* gru_bih  = (const float*)d_in[8];
    const float* gru_bhh  = (const float*)d_in[9];
    const float* conv_W   = (const float*)d_in[10];
    const float* conv_b   = (const float*)d_in[11];
    const float* out_W    = (const float*)d_in[12];
    const float* out_b    = (const float*)d_in[13];
    float* out = (float*)d_out;

    const int gat_smem = 8192 + 4096 + 64 + 32 + 4 * 128 * 20 * 4;   // 53344 B
    cudaFuncSetAttribute(gat_kernel, cudaFuncAttributeMaxDynamicSharedMemorySize, gat_smem);

    gat_kernel<<<NB * NT, 512, gat_smem>>>(x, adj, gat_W, att_src, att_dst);
    gruconv_kernel<<<NB * 8, 256>>>(gat_W, gru_Wih, gru_bih, gat_bias,
                                    gru_Whh, gru_bhh, conv_W, conv_b,
                                    out_W, out_b, out);
}

// round 13
// speedup vs baseline: 1.0477x; 1.0477x over previous
#include <cuda_runtime.h>
#include <cstdint>

#define NB 32
#define NT 8
#define NN 512
#define NF 4
#define NH 64
#define NCO 12
#define L2E 1.442695040888963f
#define C02 (0.2f * 1.442695040888963f)

// Intermediates (device globals; no allocation allowed)
__device__ __align__(16) float4 g_acc[(size_t)NB * NT * NN];   // unnormalized (alpha @ x)
__device__ __align__(16) float  g_inv[(size_t)NB * NT * NN];   // 1/softmax-sum

__device__ __forceinline__ float ex2f(float v) {
    float r; asm("ex2.approx.f32 %0, %1;" : "=f"(r) : "f"(v)); return r;
}
__device__ __forceinline__ float rcpf(float v) {
    float r; asm("rcp.approx.f32 %0, %1;" : "=f"(r) : "f"(v)); return r;
}
__device__ __forceinline__ float sigmf(float x) {           // NaN-safe at extremes
    return rcpf(1.f + ex2f(-L2E * x));
}
__device__ __forceinline__ float tanhfast(float x) {
    const float E = ex2f(fminf(2.f * L2E * x, 80.f));
    return (E - 1.f) * rcpf(E + 1.f);
}

// ---------------------------------------------------------------------------
// Kernel 1: fused GAT as (alpha @ x). One CTA per (b,t); 512 threads.
// (measured 52.8us, DRAM-bound, 64-reg/2-CTA sweet spot — unchanged)
// ---------------------------------------------------------------------------
__global__ void __launch_bounds__(512, 2)
gat_kernel(const float* __restrict__ x, const float* __restrict__ adj,
           const float* __restrict__ gatW, const float* __restrict__ attS,
           const float* __restrict__ attD)
{
    extern __shared__ char smraw[];
    float4* sX   = (float4*)smraw;                        // 512 * 16B
    float2* sS2  = (float2*)(smraw + 8192);               // 512 * 8B
    float*  sRed = (float*)(smraw + 8192 + 4096);         // 16
    float*  sWsd = (float*)(smraw + 8192 + 4096 + 64);    // 8
    float*  sPart= (float*)(smraw + 8192 + 4096 + 64 + 32); // 4*128*20

    const int tid = threadIdx.x;
    const int bt  = blockIdx.x;

    const float4* xg = (const float4*)(x + (size_t)bt * NN * NF);
    sX[tid] = xg[tid];
    if (tid < 8) {
        const int f = tid & 3;
        const float* wrow = gatW + f * NH;
        const float* av   = (tid < 4) ? attS : attD;
        float s = 0.f;
        for (int h = 0; h < NH; ++h) s += wrow[h] * av[h];
        sWsd[tid] = s;
    }
    __syncthreads();

    const float4 wsv = *(const float4*)(sWsd);
    const float4 wdv = *(const float4*)(sWsd + 4);

    float asrc;
    {
        const float4 xv = sX[tid];
        asrc = xv.x * wsv.x + xv.y * wsv.y + xv.z * wsv.z + xv.w * wsv.w;
        float2 ss; ss.x = asrc * L2E; ss.y = asrc * C02;
        sS2[tid] = ss;
    }
    __syncthreads();

    float v = asrc;
    #pragma unroll
    for (int o = 16; o; o >>= 1) v = fmaxf(v, __shfl_xor_sync(0xffffffffu, v, o));
    if ((tid & 31) == 0) sRed[tid >> 5] = v;
    __syncthreads();
    float smax = sRed[0];
    #pragma unroll
    for (int w = 1; w < 16; ++w) smax = fmaxf(smax, sRed[w]);

    const int s  = tid >> 7;        // j-split 0..3
    const int iq = tid & 127;       // i-quad
    const int i0 = iq * 4;

    float c1[4], c2[4];
    #pragma unroll
    for (int ii = 0; ii < 4; ++ii) {
        const float4 xi = sX[i0 + ii];
        const float ad = xi.x * wdv.x + xi.y * wdv.y + xi.z * wdv.z + xi.w * wdv.w;
        const float aL = ad * L2E, aL2 = ad * C02;
        const float Mlog = fmaxf(aL + smax * L2E, aL2 + smax * C02);
        c1[ii] = aL - Mlog;
        c2[ii] = aL2 - Mlog;
    }

    float ssum[4] = {0.f, 0.f, 0.f, 0.f};
    float ax[4] = {0.f, 0.f, 0.f, 0.f};
    float ay[4] = {0.f, 0.f, 0.f, 0.f};
    float az[4] = {0.f, 0.f, 0.f, 0.f};
    float aw[4] = {0.f, 0.f, 0.f, 0.f};

    const int jbeg = s * 128;
    const float4* pr = (const float4*)(adj + (size_t)bt * NN * NN)
                       + (size_t)jbeg * 128 + iq;

    #pragma unroll 1
    for (int j = jbeg; j < jbeg + 128; j += 4) {
        const float4 A0 = __ldg(pr);
        const float4 A1 = __ldg(pr + 128);
        const float4 A2 = __ldg(pr + 256);
        const float4 A3 = __ldg(pr + 384);
        pr += 512;
        #pragma unroll
        for (int u = 0; u < 4; ++u) {
            const float4 a = (u == 0) ? A0 : (u == 1) ? A1 : (u == 2) ? A2 : A3;
            const float2 sj = sS2[j + u];
            const float4 xj = sX[j + u];
            const float am[4] = {a.x, a.y, a.z, a.w};
            #pragma unroll
            for (int ii = 0; ii < 4; ++ii) {
                const float e = fmaxf(c1[ii] + sj.x, c2[ii] + sj.y);
                float p = ex2f(e);
                p = (am[ii] != 0.f) ? p : 0.f;
                ssum[ii] += p;
                ax[ii] += p * xj.x; ay[ii] += p * xj.y;
                az[ii] += p * xj.z; aw[ii] += p * xj.w;
            }
        }
    }

    if ((iq >> 5) == s) {
        const float* ap = adj + (size_t)bt * NN * NN + i0;
        #pragma unroll
        for (int ii = 0; ii < 4; ++ii) {
            const int i = i0 + ii;
            const float aii = __ldg(ap + (size_t)i * NN + ii);
            if (aii == 0.f) {
                const float2 sj = sS2[i];
                const float p = ex2f(fmaxf(c1[ii] + sj.x, c2[ii] + sj.y));
                const float4 xi = sX[i];
                ssum[ii] += p;
                ax[ii] += p * xi.x; ay[ii] += p * xi.y;
                az[ii] += p * xi.z; aw[ii] += p * xi.w;
            }
        }
    }

    float* pp = sPart + (size_t)(s * 128 + iq) * 20;
    #pragma unroll
    for (int ii = 0; ii < 4; ++ii) {
        pp[ii * 5 + 0] = ax[ii]; pp[ii * 5 + 1] = ay[ii];
        pp[ii * 5 + 2] = az[ii]; pp[ii * 5 + 3] = aw[ii];
        pp[ii * 5 + 4] = ssum[ii];
    }
    __syncthreads();

    const int q2 = tid >> 2, i2 = tid & 3;
    float vx = 0.f, vy = 0.f, vz = 0.f, vw = 0.f, sv = 0.f;
    #pragma unroll
    for (int s2 = 0; s2 < 4; ++s2) {
        const float* p2 = sPart + (size_t)(s2 * 128 + q2) * 20 + i2 * 5;
        vx += p2[0]; vy += p2[1]; vz += p2[2]; vw += p2[3]; sv += p2[4];
    }
    const size_t o = (size_t)bt * NN + tid;
    float4 av; av.x = vx; av.y = vy; av.z = vz; av.w = vw;
    g_acc[o] = av;
    g_inv[o] = 1.f / sv;
}

// ---------------------------------------------------------------------------
// Kernel 2: FUSED GRU recurrence + Conv2d(8->12, 3x3 SAME over [N,4]) +
// Linear(4->2). Block = (b, quarter of 128 n), 512 threads, grid 128.
// Mapping: conv input g[b, ci, n, :] = h_{t=ci} of GRU sequence m = b*512+n;
// sequence m reads gat data at base = (b*8 + (n>>6))*512 + (n&63)*8 + t.
// 130 threads run recurrences (rows n0-1..n0+128) into the tile;
// 512 threads then convolve (128 n x 4 co-splits of 3).
// ---------------------------------------------------------------------------
__global__ void __launch_bounds__(512)
gruconv_kernel(const float* __restrict__ gatW, const float* __restrict__ Wih,
               const float* __restrict__ bih, const float* __restrict__ gbias,
               const float* __restrict__ Whh, const float* __restrict__ bhh,
               const float* __restrict__ cW, const float* __restrict__ cB,
               const float* __restrict__ oW, const float* __restrict__ oB,
               float* __restrict__ out)
{
    __shared__ float4 sG[130 * 9];       // [local row][t(0..7), pad] = h_t
    __shared__ float4 sW4[288];          // [(ci*3+kh)*12 + co] = {w0,w1,w2,0}
    __shared__ float sCB[12], sOW[8], sOB[2];
    __shared__ float sC[48], sd[12], sWhh[48], sbhh[12];

    const int tid = threadIdx.x;
    const int b   = blockIdx.x >> 2;
    const int g   = blockIdx.x & 3;
    const int n0  = g * 128;

    if (tid < 288) {
        const int co = tid % 12, r = tid / 12, kh = r % 3, ci = r / 3;
        const float* wp = cW + (((size_t)co * NT + ci) * 3 + kh) * 3;
        float4 w; w.x = wp[0]; w.y = wp[1]; w.z = wp[2]; w.w = 0.f;
        sW4[(ci * 3 + kh) * 12 + co] = w;
    }
    if (tid < 12) sCB[tid] = cB[tid];
    if (tid < 8)  sOW[tid] = oW[tid];
    if (tid < 2)  sOB[tid] = oB[tid];
    // GRU folded weights: C = W @ Wih^T, d = Wih@bias + bih
    if (tid >= 288 && tid < 336) {
        const int k2 = tid - 288;
        const int f = k2 / 12, k = k2 % 12;
        float sacc = 0.f;
        for (int h = 0; h < NH; ++h) sacc += gatW[f * NH + h] * Wih[k * NH + h];
        sC[f * 12 + k] = sacc;
        sWhh[k2] = Whh[k2];
    }
    if (tid >= 336 && tid < 348) {
        const int k = tid - 336;
        float sacc = bih[k];
        for (int h = 0; h < NH; ++h) sacc += Wih[k * NH + h] * gbias[h];
        sd[k] = sacc;
        sbhh[k] = bhh[k];
    }
    // zero tile (covers boundary rows n=-1 / n=512)
    for (int k = tid; k < 130 * 9; k += 512) {
        float4 z = {0.f, 0.f, 0.f, 0.f};
        sG[k] = z;
    }
    __syncthreads();

    // ---- recurrences: 130 threads, one per tile row ----
    if (tid < 130) {
        const int n = n0 - 1 + tid;          // global sequence index
        if (n >= 0 && n < NN) {
            const int base = ((b * 8 + (n >> 6)) << 9) + (n & 63) * 8;
            float4 A[8];
            #pragma unroll
            for (int t = 0; t < NT; ++t) A[t] = g_acc[base + t];
            float inv[8];
            {
                const float4 I0 = *(const float4*)(g_inv + base);
                const float4 I1 = *(const float4*)(g_inv + base + 4);
                inv[0] = I0.x; inv[1] = I0.y; inv[2] = I0.z; inv[3] = I0.w;
                inv[4] = I1.x; inv[5] = I1.y; inv[6] = I1.z; inv[7] = I1.w;
            }
            float h[4] = {0.f, 0.f, 0.f, 0.f};
            float4* row = sG + tid * 9;
            #pragma unroll
            for (int t = 0; t < NT; ++t) {
                const float4 a = A[t];
                const float iv = inv[t];
                float gx[12];
                #pragma unroll
                for (int k = 0; k < 12; ++k)
                    gx[k] = iv * (a.x * sC[k] + a.y * sC[12 + k] + a.z * sC[24 + k] + a.w * sC[36 + k]) + sd[k];
                float hn[4];
                #pragma unroll
                for (int c = 0; c < 4; ++c) {
                    float ghr = sbhh[c]     + h[0]*sWhh[c*4]     + h[1]*sWhh[c*4+1]     + h[2]*sWhh[c*4+2]     + h[3]*sWhh[c*4+3];
                    float ghz = sbhh[4 + c] + h[0]*sWhh[(4+c)*4] + h[1]*sWhh[(4+c)*4+1] + h[2]*sWhh[(4+c)*4+2] + h[3]*sWhh[(4+c)*4+3];
                    float ghn = sbhh[8 + c] + h[0]*sWhh[(8+c)*4] + h[1]*sWhh[(8+c)*4+1] + h[2]*sWhh[(8+c)*4+2] + h[3]*sWhh[(8+c)*4+3];
                    float rr = sigmf(gx[c] + ghr);
                    float zz = sigmf(gx[4 + c] + ghz);
                    float nc = tanhfast(gx[8 + c] + rr * ghn);
                    hn[c] = (1.f - zz) * nc + zz * h[c];
                }
                #pragma unroll
                for (int c = 0; c < 4; ++c) h[c] = hn[c];
                float4 hv; hv.x = h[0]; hv.y = h[1]; hv.z = h[2]; hv.w = h[3];
                row[t] = hv;                 // channel ci = t
            }
        }
    }
    __syncthreads();

    // ---- conv + linear: 512 threads = (128 n) x (4 co-splits of 3) ----
    const int nloc = tid & 127;
    const int cos  = tid >> 7;

    float y[3][4];
    #pragma unroll
    for (int cc = 0; cc < 3; ++cc) {
        const float cb = sCB[cos * 3 + cc];
        y[cc][0] = cb; y[cc][1] = cb; y[cc][2] = cb; y[cc][3] = cb;
    }

    #pragma unroll
    for (int ci = 0; ci < NT; ++ci) {
        #pragma unroll
        for (int kh = 0; kh < 3; ++kh) {
            const float4 vv = sG[(nloc + kh) * 9 + ci];
            #pragma unroll
            for (int cc = 0; cc < 3; ++cc) {
                const float4 w4 = sW4[(ci * 3 + kh) * 12 + cos * 3 + cc];
                y[cc][0] += vv.x * w4.y + vv.y * w4.z;
                y[cc][1] += vv.x * w4.x + vv.y * w4.y + vv.z * w4.z;
                y[cc][2] += vv.y * w4.x + vv.z * w4.y + vv.w * w4.z;
                y[cc][3] += vv.z * w4.x + vv.w * w4.y;
            }
        }
    }

    const int n = n0 + nloc;
    float* op = out + (((size_t)b * NCO + cos * 3) * NN + n) * 2;
    #pragma unroll
    for (int cc = 0; cc < 3; ++cc) {
        float2 o;
        o.x = sOB[0] + y[cc][0]*sOW[0] + y[cc][1]*sOW[1] + y[cc][2]*sOW[2] + y[cc][3]*sOW[3];
        o.y = sOB[1] + y[cc][0]*sOW[4] + y[cc][1]*sOW[5] + y[cc][2]*sOW[6] + y[cc][3]*sOW[7];
        *(float2*)(op + (size_t)cc * (NN * 2)) = o;
    }
}

// ---------------------------------------------------------------------------
extern "C" void kernel_launch(void* const* d_in, const int* in_sizes, int n_in,
                              void* d_out, int out_size)
{
    const float* x        = (const float*)d_in[0];
    const float* adj      = (const float*)d_in[1];
    const float* gat_W    = (const float*)d_in[2];
    const float* att_src  = (const float*)d_in[3];
    const float* att_dst  = (const float*)d_in[4];
    const float* gat_bias = (const float*)d_in[5];
    const float* gru_Wih  = (const float*)d_in[6];
    const float* gru_Whh  = (const float*)d_in[7];
    const float* gru_bih  = (const float*)d_in[8];
    const float* gru_bhh  = (const float*)d_in[9];
    const float* conv_W   = (const float*)d_in[10];
    const float* conv_b   = (const float*)d_in[11];
    const float* out_W    = (const float*)d_in[12];
    const float* out_b    = (const float*)d_in[13];
    float* out = (float*)d_out;

    const int gat_smem = 8192 + 4096 + 64 + 32 + 4 * 128 * 20 * 4;   // 53344 B
    cudaFuncSetAttribute(gat_kernel, cudaFuncAttributeMaxDynamicSharedMemorySize, gat_smem);

    gat_kernel<<<NB * NT, 512, gat_smem>>>(x, adj, gat_W, att_src, att_dst);
    gruconv_kernel<<<NB * 4, 512>>>(gat_W, gru_Wih, gru_bih, gat_bias,
                                    gru_Whh, gru_bhh, conv_W, conv_b,
                                    out_W, out_b, out);
}